// round 4
// baseline (speedup 1.0000x reference)
#include <cuda_runtime.h>
#include <cstdint>

#define BB 64
#define SS 512
#define HH 768
#define EE 512
#define TT 256

// Scratch (allocation-free rule: __device__ globals)
__device__ float g_pooled[(size_t)BB * TT * HH];   // tf32-rounded pooled A
__device__ float g_wcvt[(size_t)EE * HH];          // tf32-rounded W

__device__ __forceinline__ unsigned f2tf32(float x) {
    unsigned u;
    asm("cvt.rna.tf32.f32 %0, %1;" : "=r"(u) : "f"(x));
    return u;
}

// ---------------------------------------------------------------------------
// Kernel 1: segment-mean pooling (word_ids sorted -> binary search range).
// Emits tf32-rounded values so the GEMM stages raw bits.
// ---------------------------------------------------------------------------
__global__ __launch_bounds__(192) void pool_kernel(
        const float* __restrict__ hs,   // [B, S, H]
        const int*   __restrict__ wid,  // [B, S]
        const int*   __restrict__ tlen) // [B]
{
    const int t   = blockIdx.x;
    const int b   = blockIdx.y;
    const int tid = threadIdx.x;

    const int* w = wid + b * SS;
    int l = 0, r = SS;
    while (l < r) { int m = (l + r) >> 1; if (w[m] < t) l = m + 1; else r = m; }
    const int lo = l;
    r = SS;
    while (l < r) { int m = (l + r) >> 1; if (w[m] <= t) l = m + 1; else r = m; }
    const int hi = l;

    const bool valid = (t < tlen[b]) && (hi > lo);
    const float inv = valid ? (1.0f / (float)(hi - lo)) : 0.0f;

    float4 acc = make_float4(0.f, 0.f, 0.f, 0.f);
    if (valid) {
        const float* p = hs + ((size_t)b * SS + lo) * HH + tid * 4;
        for (int i = lo; i < hi; ++i, p += HH) {
            float4 v = *(const float4*)p;
            acc.x += v.x; acc.y += v.y; acc.z += v.z; acc.w += v.w;
        }
    }
    float4 o;
    o.x = __uint_as_float(f2tf32(acc.x * inv));
    o.y = __uint_as_float(f2tf32(acc.y * inv));
    o.z = __uint_as_float(f2tf32(acc.z * inv));
    o.w = __uint_as_float(f2tf32(acc.w * inv));
    float* outp = g_pooled + ((size_t)b * TT + t) * HH + tid * 4;
    *(float4*)outp = o;
}

// ---------------------------------------------------------------------------
// Kernel 1b: pre-round W to tf32 once.
// ---------------------------------------------------------------------------
__global__ __launch_bounds__(256) void wcvt_kernel(const float* __restrict__ W) {
    int i = blockIdx.x * 256 + threadIdx.x;      // float4 index
    float4 v = ((const float4*)W)[i];
    float4 o;
    o.x = __uint_as_float(f2tf32(v.x));
    o.y = __uint_as_float(f2tf32(v.y));
    o.z = __uint_as_float(f2tf32(v.z));
    o.w = __uint_as_float(f2tf32(v.w));
    ((float4*)g_wcvt)[i] = o;
}

// ---------------------------------------------------------------------------
// Kernel 2: TF32 GEMM, out[m,e] = pooled[m,:] . W[e,:] + bias[e]
// M=16384, N=512, K=768. Block 128x128, BK=16, 4 warps, warp tile 64x64.
// SMEM holds operands pre-permuted into mma.m16n8k8 fragment layout:
//   A frag = one LDS.128 / tile, B frag = one LDS.64 / tile.
// XOR swizzle keeps consumer loads conflict-free, producer STS <=2-way.
// Double-buffered SMEM + register prefetch: 1 __syncthreads per k-block.
// ---------------------------------------------------------------------------
#define BM 128
#define BN 128
#define BK 16
#define NKB (HH / BK)   // 48

__global__ __launch_bounds__(128) void gemm_tf32_kernel(
        const float* __restrict__ bias, // [E]
        const int*   __restrict__ tlen, // [B]
        float*       __restrict__ out)  // [M, E]
{
    const int tid = threadIdx.x;
    const int n0  = blockIdx.x * BN;
    const int m0  = blockIdx.y * BM;
    float* cbase = out + (size_t)m0 * EE + n0;

    const int batch = m0 / TT;
    const int t0    = m0 % TT;

    if (t0 >= tlen[batch]) {
        // fully masked tile: output = bias broadcast
        #pragma unroll 4
        for (int i = tid; i < BM * (BN / 4); i += 128) {
            int r = i >> 5;            // BN/4 = 32
            int c = (i & 31) * 4;
            *(float4*)(cbase + (size_t)r * EE + c) = *(const float4*)(bias + n0 + c);
        }
        return;
    }

    // Fragment-layout staging buffers (double buffered): 2 x 8KB each.
    __shared__ __align__(16) unsigned sA[2][2048];  // [kt(2)][mt(8)][128 words]
    __shared__ __align__(16) unsigned sB[2][2048];  // [kt(2)][nt(16)][64 words]

    const float* Ag = g_pooled + (size_t)(m0 + tid) * HH;   // one row per thread
    const float* Bg = g_wcvt   + (size_t)(n0 + tid) * HH;   // one row per thread

    // loader-side indices (thread = row)
    const int mt_l = tid >> 4;        // A m-tile 0..7
    const int gp   = tid & 7;         // row % 8 (same for A and B)
    const int mh   = (tid >> 3) & 1;  // (row%16) >= 8
    const int nt_l = tid >> 3;        // B n-tile 0..15

    // compute-side indices
    const int wid  = tid >> 5;
    const int lane = tid & 31;
    const int wm = wid >> 1;          // 0..1
    const int wn = wid & 1;           // 0..1
    const int g  = lane >> 2;
    const int tg = lane & 3;

    float acc[4][8][4];
    #pragma unroll
    for (int i = 0; i < 4; ++i)
        #pragma unroll
        for (int j = 0; j < 8; ++j)
            #pragma unroll
            for (int q = 0; q < 4; ++q) acc[i][j][q] = 0.0f;

    float4 pa[4], pb[4];

    // prologue: load k-block 0
    #pragma unroll
    for (int q = 0; q < 4; ++q) {
        pa[q] = *(const float4*)(Ag + q * 4);
        pb[q] = *(const float4*)(Bg + q * 4);
    }

    // STS: scatter prefetch registers into fragment layout of buffer bb
    #define STS_BLOCK(bb)                                                        \
    {                                                                            \
        _Pragma("unroll")                                                        \
        for (int q = 0; q < 4; ++q) {                                            \
            const int kt = q >> 1, kh = q & 1;                                   \
            const int ra = mh + 2 * kh;                                          \
            const int baseA = (kt * 8 + mt_l) * 128;                             \
            const int baseB = (kt * 16 + nt_l) * 64;                             \
            const float va[4] = {pa[q].x, pa[q].y, pa[q].z, pa[q].w};            \
            const float vb[4] = {pb[q].x, pb[q].y, pb[q].z, pb[q].w};            \
            _Pragma("unroll")                                                    \
            for (int c = 0; c < 4; ++c) {                                        \
                sA[bb][baseA + ((((gp * 4 + c) * 4 + ra)) ^ (gp << 2))] =        \
                    __float_as_uint(va[c]);                                      \
                sB[bb][baseB + ((((gp * 4 + c) * 2 + kh)) ^ ((nt_l & 3) << 1))] =\
                    __float_as_uint(vb[c]);                                      \
            }                                                                    \
        }                                                                        \
    }

    STS_BLOCK(0);
    __syncthreads();

    #pragma unroll 1
    for (int kb = 0; kb < NKB; ++kb) {
        const int cur = kb & 1;

        if (kb + 1 < NKB) {
            const float* Ap = Ag + (kb + 1) * BK;
            const float* Bp = Bg + (kb + 1) * BK;
            #pragma unroll
            for (int q = 0; q < 4; ++q) {
                pa[q] = *(const float4*)(Ap + q * 4);
                pb[q] = *(const float4*)(Bp + q * 4);
            }
        }

        #pragma unroll
        for (int kt = 0; kt < 2; ++kt) {
            unsigned af[4][4];
            unsigned bf[8][2];
            #pragma unroll
            for (int i = 0; i < 4; ++i) {
                uint4 v = *(const uint4*)&sA[cur][(kt * 8 + wm * 4 + i) * 128 +
                                                  ((lane * 4) ^ (g << 2))];
                af[i][0] = v.x; af[i][1] = v.y; af[i][2] = v.z; af[i][3] = v.w;
            }
            #pragma unroll
            for (int j = 0; j < 8; ++j) {
                const int nt = wn * 8 + j;
                uint2 v = *(const uint2*)&sB[cur][(kt * 16 + nt) * 64 +
                                                  ((lane * 2) ^ ((nt & 3) << 1))];
                bf[j][0] = v.x; bf[j][1] = v.y;
            }
            #pragma unroll
            for (int i = 0; i < 4; ++i)
                #pragma unroll
                for (int j = 0; j < 8; ++j) {
                    asm volatile(
                        "mma.sync.aligned.m16n8k8.row.col.f32.tf32.tf32.f32 "
                        "{%0,%1,%2,%3}, {%4,%5,%6,%7}, {%8,%9}, {%0,%1,%2,%3};"
                        : "+f"(acc[i][j][0]), "+f"(acc[i][j][1]),
                          "+f"(acc[i][j][2]), "+f"(acc[i][j][3])
                        : "r"(af[i][0]), "r"(af[i][1]),
                          "r"(af[i][2]), "r"(af[i][3]),
                          "r"(bf[j][0]), "r"(bf[j][1]));
                }
        }

        if (kb + 1 < NKB) STS_BLOCK(cur ^ 1);
        __syncthreads();
    }

    // Epilogue: bias add + float2 stores
    float2 bv[8];
    #pragma unroll
    for (int j = 0; j < 8; ++j)
        bv[j] = *(const float2*)(bias + n0 + (wn * 8 + j) * 8 + 2 * tg);

    #pragma unroll
    for (int i = 0; i < 4; ++i) {
        const int r0 = (wm * 4 + i) * 16 + g;
        const int r1 = r0 + 8;
        #pragma unroll
        for (int j = 0; j < 8; ++j) {
            const int col = (wn * 8 + j) * 8 + 2 * tg;
            float2 v0 = make_float2(acc[i][j][0] + bv[j].x, acc[i][j][1] + bv[j].y);
            float2 v1 = make_float2(acc[i][j][2] + bv[j].x, acc[i][j][3] + bv[j].y);
            *(float2*)(cbase + (size_t)r0 * EE + col) = v0;
            *(float2*)(cbase + (size_t)r1 * EE + col) = v1;
        }
    }
}

// ---------------------------------------------------------------------------
extern "C" void kernel_launch(void* const* d_in, const int* in_sizes, int n_in,
                              void* d_out, int out_size) {
    const float* hs   = (const float*)d_in[0];  // [64, 512, 768]
    const int*   wid  = (const int*)  d_in[1];  // [64, 512]
    const int*   tlen = (const int*)  d_in[2];  // [64]
    const float* Wm   = (const float*)d_in[3];  // [512, 768]
    const float* bias = (const float*)d_in[4];  // [512]
    float*       out  = (float*)d_out;          // [64, 256, 512]

    pool_kernel<<<dim3(TT, BB), 192>>>(hs, wid, tlen);
    wcvt_kernel<<<(EE * HH / 4) / 256, 256>>>(Wm);
    gemm_tf32_kernel<<<dim3(EE / BN, (BB * TT) / BM), 128>>>(bias, tlen, out);
}